// round 9
// baseline (speedup 1.0000x reference)
#include <cuda_runtime.h>
#include <cuda_bf16.h>
#include <cstdint>
#include <cstddef>

#define NBATCH 64
#define NTOT   8192
#define THRESH 0.02f
#define KT     64
#define NCH_E  128                 // einsum chunks (K=8192)
#define NCH    176                 // + 48 stim chunks (K=3072)
#define HALF   88                  // chunks per k-slice
#define MTILE  128

// smem per buffer: Ahi 16K | Alo 16K | Bhi 8K | Blo 8K  (SW128, 128B rows)
#define WHI_OFF 0
#define WLO_OFF 16384
#define ZHI_OFF 32768
#define ZLO_OFF 40960
#define BUFB    49152
#define SMEM_TOTAL (2 * BUFB)      // 98304

__device__ float g_gatepart[16][4];        // per-slice gate partial sums
__device__ float g_accum[NBATCH * NTOT];
__device__ float g_znew[NBATCH * NTOT];

// ---------------- helpers ----------------
static __device__ __forceinline__ uint32_t smem_u32(const void* p) {
    uint32_t a;
    asm("{ .reg .u64 t; cvta.to.shared.u64 t, %1; cvt.u32.u64 %0, t; }" : "=r"(a) : "l"(p));
    return a;
}
#define SWZ(o) ((o) ^ (((o) >> 3) & 0x70))

static __device__ __forceinline__ void ldsm4(uint32_t* r, uint32_t addr) {
    asm volatile("ldmatrix.sync.aligned.m8n8.x4.shared.b16 {%0,%1,%2,%3}, [%4];"
                 : "=r"(r[0]), "=r"(r[1]), "=r"(r[2]), "=r"(r[3]) : "r"(addr));
}
static __device__ __forceinline__ void mma_bf16(float* d, const uint32_t* a,
                                                uint32_t b0, uint32_t b1) {
    asm volatile("mma.sync.aligned.m16n8k16.row.col.f32.bf16.bf16.f32 "
                 "{%0,%1,%2,%3}, {%4,%5,%6,%7}, {%8,%9}, {%0,%1,%2,%3};"
                 : "+f"(d[0]), "+f"(d[1]), "+f"(d[2]), "+f"(d[3])
                 : "r"(a[0]), "r"(a[1]), "r"(a[2]), "r"(a[3]), "r"(b0), "r"(b1));
}
static __device__ __forceinline__ void pref_l2(const void* p) {
    asm volatile("prefetch.global.L2 [%0];" :: "l"(p));
}

// gate value for area i from partials
static __device__ __forceinline__ float gate_of(int i) {
    float s = 0.f;
#pragma unroll
    for (int sl = 0; sl < 16; sl++) s += g_gatepart[sl][i];
    return (s * (1.0f / 131072.0f) > THRESH) ? 1.f : 0.f;
}

// split (a,b) into packed bf16 hi + lo-residual pair (lo half of reg = a)
static __device__ __forceinline__ void split2(float a, float b, uint32_t& hp, uint32_t& lp) {
    asm("cvt.rn.bf16x2.f32 %0, %1, %2;" : "=r"(hp) : "f"(b), "f"(a));
    float ha = __uint_as_float(hp << 16);
    float hb = __uint_as_float(hp & 0xffff0000u);
    float la = a - ha;
    float lb = b - hb;
    asm("cvt.rn.bf16x2.f32 %0, %1, %2;" : "=r"(lp) : "f"(lb), "f"(la));
}
static __device__ __forceinline__ void split4(float4 f, uint2& h, uint2& l) {
    split2(f.x, f.y, h.x, l.x);
    split2(f.z, f.w, h.y, l.y);
}

// ---------------- init: zero accum (all blocks) + gate partials (blocks 0..63) ----------------
__global__ void init_kernel(const float* __restrict__ Z) {
    int blk = blockIdx.x, t = threadIdx.x;
    int idx = blk * 256 + t;
    float4* p = (float4*)g_accum;
#pragma unroll
    for (int j = 0; j < 4; j++) p[idx * 4 + j] = make_float4(0.f, 0.f, 0.f, 0.f);

    if (blk < 64) {
        int area = blk & 3, slice = blk >> 2;
        float s = 0.f;
#pragma unroll
        for (int it = 0; it < 8; it++) {
            int f = t + 256 * it;
            int b = slice * 4 + (f >> 9), a4 = f & 511;
            float4 v = *(const float4*)(Z + (size_t)b * NTOT + (size_t)area * 2048 + a4 * 4);
            s += fabsf(v.x) + fabsf(v.y) + fabsf(v.z) + fabsf(v.w);
        }
#pragma unroll
        for (int o = 16; o; o >>= 1) s += __shfl_xor_sync(0xffffffffu, s, o);
        __shared__ float ws[8];
        if ((t & 31) == 0) ws[t >> 5] = s;
        __syncthreads();
        if (t == 0) {
            float tot = 0.f;
            for (int w = 0; w < 8; w++) tot += ws[w];
            g_gatepart[slice][area] = tot;
        }
    }
}

// ---------------- main HMMA kernel ----------------
__global__ __launch_bounds__(256, 1)
void main_kernel(const float* __restrict__ x, const float* __restrict__ Z,
                 const float* __restrict__ rw, const float* __restrict__ W,
                 const float* __restrict__ Mk)
{
    extern __shared__ char smem[];
    const uint32_t sb = smem_u32(smem);
    const int t = threadIdx.x, wid = t >> 5, lid = t & 31;
    const int ct = blockIdx.x >> 1;         // M-tile 0..63
    const int ks = blockIdx.x & 1;          // k-slice
    const int n0 = ct * MTILE;
    const int o = ct >> 4;
    const int u0 = (ct & 15) * MTILE;

    float gates[4];
#pragma unroll
    for (int i = 0; i < 4; i++) gates[i] = gate_of(i);

    // coalesced loader indices: warp lanes contiguous in memory
    const int lr16 = t >> 4;                // 0..15
    const int lk = t & 15;                  // float4 slot within KT

    float4 wv[8], mv[8], zv[4];
    uint2 ah2[8], al2[8], zh2[4], zl2[4];

    auto ldg = [&](int c) {
        if (c < NCH_E) {
            int k0 = c * KT, i = k0 >> 11, kl = k0 & 2047;
            const size_t base = ((size_t)(o * 4 + i) * 2048 + u0) * 2048 + kl + lk * 4;
#pragma unroll
            for (int v = 0; v < 8; v++) {
                size_t off = base + (size_t)(v * 16 + lr16) * 2048;
                wv[v] = *(const float4*)(W + off);
                mv[v] = *(const float4*)(Mk + off);
            }
#pragma unroll
            for (int v = 0; v < 4; v++)
                zv[v] = *(const float4*)(Z + (size_t)(v * 16 + lr16) * NTOT + k0 + lk * 4);
        } else {
            int k0 = (c - NCH_E) * KT;
#pragma unroll
            for (int v = 0; v < 8; v++)
                wv[v] = *(const float4*)(rw + (size_t)(n0 + v * 16 + lr16) * 3072 + k0 + lk * 4);
#pragma unroll
            for (int v = 0; v < 4; v++)
                zv[v] = *(const float4*)(x + (size_t)(v * 16 + lr16) * 3072 + k0 + lk * 4);
        }
    };

    // L2 prefetch for chunk c (distance-2 pipeline, no register cost)
    auto pref = [&](int c) {
        if (c < NCH_E) {
            int k0 = c * KT, i = k0 >> 11, kl = k0 & 2047;
            const size_t base = ((size_t)(o * 4 + i) * 2048 + u0) * 2048 + kl + lk * 4;
#pragma unroll
            for (int v = 0; v < 8; v++) {
                size_t off = base + (size_t)(v * 16 + lr16) * 2048;
                pref_l2(W + off);
                pref_l2(Mk + off);
            }
        } else {
            int k0 = (c - NCH_E) * KT;
#pragma unroll
            for (int v = 0; v < 8; v++)
                pref_l2(rw + (size_t)(n0 + v * 16 + lr16) * 3072 + k0 + lk * 4);
        }
    };

    auto cvtA = [&](int v, bool einsum) {
        float4 f = wv[v];
        if (einsum) {
            float4 m = mv[v];
            f.x *= __saturatef(m.x); f.y *= __saturatef(m.y);
            f.z *= __saturatef(m.z); f.w *= __saturatef(m.w);
        }
        split4(f, ah2[v], al2[v]);
    };
    auto cvtZ = [&](int v, float zg) {
        float4 f = zv[v];
        f.x *= zg; f.y *= zg; f.z *= zg; f.w *= zg;
        split4(f, zh2[v], zl2[v]);
    };

    auto sts = [&](uint32_t buf) {
#pragma unroll
        for (int v = 0; v < 8; v++) {
            uint32_t sw = SWZ((uint32_t)((v * 16 + lr16) * 128 + lk * 8));
            asm volatile("st.shared.v2.b32 [%0], {%1,%2};" ::
                         "r"(buf + WHI_OFF + sw), "r"(ah2[v].x), "r"(ah2[v].y) : "memory");
            asm volatile("st.shared.v2.b32 [%0], {%1,%2};" ::
                         "r"(buf + WLO_OFF + sw), "r"(al2[v].x), "r"(al2[v].y) : "memory");
        }
#pragma unroll
        for (int v = 0; v < 4; v++) {
            uint32_t sw = SWZ((uint32_t)((v * 16 + lr16) * 128 + lk * 8));
            asm volatile("st.shared.v2.b32 [%0], {%1,%2};" ::
                         "r"(buf + ZHI_OFF + sw), "r"(zh2[v].x), "r"(zh2[v].y) : "memory");
            asm volatile("st.shared.v2.b32 [%0], {%1,%2};" ::
                         "r"(buf + ZLO_OFF + sw), "r"(zl2[v].x), "r"(zl2[v].y) : "memory");
        }
    };

    // warp tile: mw in 0..3 (32 cols), nw in 0..1 (32 batches)
    const int mw = wid & 3, nw = wid >> 2;
    const int lr = lid & 15, lh = lid >> 4;
    const uint32_t a_row0 = (uint32_t)((mw * 32 + lr) * 128 + lh * 16);
    const uint32_t a_row1 = a_row0 + 16 * 128;
    const uint32_t b_row0 = (uint32_t)((nw * 32 + lr) * 128 + lh * 16);
    const uint32_t b_row1 = b_row0 + 16 * 128;

    float acc[8][4];
#pragma unroll
    for (int i = 0; i < 8; i++)
#pragma unroll
        for (int j = 0; j < 4; j++) acc[i][j] = 0.f;

    auto mma_kk = [&](uint32_t buf, int kk) {
        const uint32_t ko = (uint32_t)(kk * 32);
        uint32_t ah0[4], ah1[4], al0[4], al1[4];
        uint32_t bh0[4], bh1[4], bl0[4], bl1[4];
        ldsm4(ah0, buf + WHI_OFF + SWZ(a_row0 + ko));
        ldsm4(ah1, buf + WHI_OFF + SWZ(a_row1 + ko));
        ldsm4(bh0, buf + ZHI_OFF + SWZ(b_row0 + ko));
        ldsm4(bh1, buf + ZHI_OFF + SWZ(b_row1 + ko));
        ldsm4(al0, buf + WLO_OFF + SWZ(a_row0 + ko));
        ldsm4(al1, buf + WLO_OFF + SWZ(a_row1 + ko));
        ldsm4(bl0, buf + ZLO_OFF + SWZ(b_row0 + ko));
        ldsm4(bl1, buf + ZLO_OFF + SWZ(b_row1 + ko));
        mma_bf16(acc[0], ah0, bh0[0], bh0[2]);
        mma_bf16(acc[1], ah0, bh0[1], bh0[3]);
        mma_bf16(acc[2], ah0, bh1[0], bh1[2]);
        mma_bf16(acc[3], ah0, bh1[1], bh1[3]);
        mma_bf16(acc[4], ah1, bh0[0], bh0[2]);
        mma_bf16(acc[5], ah1, bh0[1], bh0[3]);
        mma_bf16(acc[6], ah1, bh1[0], bh1[2]);
        mma_bf16(acc[7], ah1, bh1[1], bh1[3]);
        mma_bf16(acc[0], ah0, bl0[0], bl0[2]);
        mma_bf16(acc[1], ah0, bl0[1], bl0[3]);
        mma_bf16(acc[2], ah0, bl1[0], bl1[2]);
        mma_bf16(acc[3], ah0, bl1[1], bl1[3]);
        mma_bf16(acc[4], ah1, bl0[0], bl0[2]);
        mma_bf16(acc[5], ah1, bl0[1], bl0[3]);
        mma_bf16(acc[6], ah1, bl1[0], bl1[2]);
        mma_bf16(acc[7], ah1, bl1[1], bl1[3]);
        mma_bf16(acc[0], al0, bh0[0], bh0[2]);
        mma_bf16(acc[1], al0, bh0[1], bh0[3]);
        mma_bf16(acc[2], al0, bh1[0], bh1[2]);
        mma_bf16(acc[3], al0, bh1[1], bh1[3]);
        mma_bf16(acc[4], al1, bh0[0], bh0[2]);
        mma_bf16(acc[5], al1, bh0[1], bh0[3]);
        mma_bf16(acc[6], al1, bh1[0], bh1[2]);
        mma_bf16(acc[7], al1, bh1[1], bh1[3]);
    };

    const int c0 = ks * HALF, c1 = c0 + HALF;

    // prologue: stage chunk c0
    ldg(c0);
    if (c0 + 1 < c1) pref(c0 + 1);
    {
        bool e0 = (c0 < NCH_E);
        float zg0 = e0 ? gates[(c0 * KT) >> 11] : 1.f;
#pragma unroll
        for (int v = 0; v < 8; v++) cvtA(v, e0);
#pragma unroll
        for (int v = 0; v < 4; v++) cvtZ(v, zg0);
        sts(sb);
    }
    __syncthreads();

    for (int c = c0; c < c1; c++) {
        const int p = (c - c0) & 1;
        const uint32_t buf = sb + (uint32_t)p * BUFB;
        const uint32_t nbuf = sb + (uint32_t)(p ^ 1) * BUFB;
        const bool have_next = (c + 1 < c1);
        bool ne = false; float nzg = 1.f;
        if (have_next) {
            ldg(c + 1);                      // coalesced loads, issued early
            ne = (c + 1 < NCH_E);
            nzg = ne ? gates[((c + 1) * KT) >> 11] : 1.f;
        }
        if (c + 2 < c1) pref(c + 2);         // distance-2 L2 prefetch
        mma_kk(buf, 0);
        mma_kk(buf, 1);
        mma_kk(buf, 2);
        if (have_next) {
            cvtA(0, ne); cvtA(1, ne); cvtA(2, ne); cvtA(3, ne);
            cvtZ(0, nzg); cvtZ(1, nzg);
        }
        mma_kk(buf, 3);
        if (have_next) {
            cvtA(4, ne); cvtA(5, ne); cvtA(6, ne); cvtA(7, ne);
            cvtZ(2, nzg); cvtZ(3, nzg);
            sts(nbuf);
        }
        __syncthreads();
    }

    // epilogue: spread atomics into g_accum
    const int mbase = n0 + mw * 32;
    const int nbase = nw * 32;
    const int r = lid >> 2, cp = (lid & 3) * 2;
#pragma unroll
    for (int mt = 0; mt < 2; mt++) {
#pragma unroll
        for (int nt = 0; nt < 4; nt++) {
            const float* cc = acc[mt * 4 + nt];
            int m = mbase + mt * 16 + r;
            int nb = nbase + nt * 8 + cp;
            atomicAdd(&g_accum[(size_t)nb * NTOT + m],           cc[0]);
            atomicAdd(&g_accum[(size_t)(nb + 1) * NTOT + m],     cc[1]);
            atomicAdd(&g_accum[(size_t)nb * NTOT + m + 8],       cc[2]);
            atomicAdd(&g_accum[(size_t)(nb + 1) * NTOT + m + 8], cc[3]);
        }
    }
}

// ---------------- combine: bias/decay/tanh ----------------
__global__ void combine_kernel(const float* __restrict__ Z, const float* __restrict__ F,
                               const float* __restrict__ rb, const float* __restrict__ bias)
{
    int idx = blockIdx.x * 256 + threadIdx.x;
    int rest = idx & 2047;
    int n4 = rest * 4;
    int o = n4 >> 11;
    float g = gate_of(o);
    float4 a  = ((const float4*)g_accum)[idx];
    float4 rv = *(const float4*)(rb + n4);
    float4 bv = *(const float4*)(bias + n4);
    float4 Fv = ((const float4*)F)[idx];
    float4 Zv = ((const float4*)Z)[idx];
    float4 outv;
    outv.x = tanhf(a.x + rv.x + bv.x * g - 0.8f * Fv.x - 0.4f * Zv.x);
    outv.y = tanhf(a.y + rv.y + bv.y * g - 0.8f * Fv.y - 0.4f * Zv.y);
    outv.z = tanhf(a.z + rv.z + bv.z * g - 0.8f * Fv.z - 0.4f * Zv.z);
    outv.w = tanhf(a.w + rv.w + bv.w * g - 0.8f * Fv.w - 0.4f * Zv.w);
    ((float4*)g_znew)[idx] = outv;
}

// ---------------- output projection (1024 threads for latency coverage) ----------------
__global__ void out_kernel(const float* __restrict__ out_w, const float* __restrict__ out_b,
                           float* __restrict__ out)
{
    int b = blockIdx.x, t = threadIdx.x;
    float p[11];
#pragma unroll
    for (int j = 0; j < 11; j++) p[j] = 0.f;
    const float4* zr = (const float4*)(g_znew + (size_t)b * NTOT);
#pragma unroll
    for (int it = 0; it < 2; it++) {
        int f4 = t + 1024 * it;
        float4 z = zr[f4];
#pragma unroll
        for (int j = 0; j < 11; j++) {
            float4 w = ((const float4*)(out_w + (size_t)j * NTOT))[f4];
            p[j] += z.x * w.x + z.y * w.y + z.z * w.z + z.w * w.w;
        }
    }
    __shared__ float red[11 * 32];
#pragma unroll
    for (int j = 0; j < 11; j++) {
        float v = p[j];
#pragma unroll
        for (int o = 16; o; o >>= 1) v += __shfl_xor_sync(0xffffffffu, v, o);
        if ((t & 31) == 0) red[j * 32 + (t >> 5)] = v;
    }
    __syncthreads();
    if (t < 11) {
        float r = out_b[t];
        for (int w = 0; w < 32; w++) r += red[t * 32 + w];
        out[(size_t)b * 11 + t] = (t < 10) ? r : 1.0f / (1.0f + expf(-r));
    }
}

// ---------------- launch ----------------
extern "C" void kernel_launch(void* const* d_in, const int* in_sizes, int n_in,
                              void* d_out, int out_size) {
    const float* x      = (const float*)d_in[0];
    const float* Z      = (const float*)d_in[1];
    const float* Fstate = (const float*)d_in[2];
    const float* rw     = (const float*)d_in[3];
    const float* rb     = (const float*)d_in[4];
    const float* W      = (const float*)d_in[5];
    const float* Mk     = (const float*)d_in[6];
    const float* bias_d = (const float*)d_in[7];
    const float* out_w  = (const float*)d_in[8];
    const float* out_b  = (const float*)d_in[9];
    float* out = (float*)d_out;

    cudaFuncSetAttribute(main_kernel, cudaFuncAttributeMaxDynamicSharedMemorySize, SMEM_TOTAL);

    init_kernel<<<128, 256>>>(Z);
    main_kernel<<<128, 256, SMEM_TOTAL>>>(x, Z, rw, W, Mk);
    combine_kernel<<<512, 256>>>(Z, Fstate, rb, bias_d);
    out_kernel<<<NBATCH, 1024>>>(out_w, out_b, out);
}

// round 10
// speedup vs baseline: 1.0503x; 1.0503x over previous
#include <cuda_runtime.h>
#include <cuda_bf16.h>
#include <cstdint>
#include <cstddef>

#define NBATCH 64
#define NTOT   8192
#define THRESH 0.02f
#define KT     64
#define MTILE  64
#define HALF   88                  // 64 einsum + 24 stim chunks per k-slice

// smem per buffer: Ahi 8K | Alo 8K | Bhi 8K | Blo 8K  (128B rows, SW128)
#define AHI_OFF 0
#define ALO_OFF 8192
#define BHI_OFF 16384
#define BLO_OFF 24576
#define BUFB    32768
#define SMEM_TOTAL (2 * BUFB)      // 65536 -> 2 CTAs/SM

__device__ float g_gatepart[16][4];
__device__ float g_accum[NBATCH * NTOT];
__device__ float g_znew[NBATCH * NTOT];

// ---------------- helpers ----------------
static __device__ __forceinline__ uint32_t smem_u32(const void* p) {
    uint32_t a;
    asm("{ .reg .u64 t; cvta.to.shared.u64 t, %1; cvt.u32.u64 %0, t; }" : "=r"(a) : "l"(p));
    return a;
}
#define SWZ(o) ((o) ^ (((o) >> 3) & 0x70))

static __device__ __forceinline__ void ldsm4(uint32_t* r, uint32_t addr) {
    asm volatile("ldmatrix.sync.aligned.m8n8.x4.shared.b16 {%0,%1,%2,%3}, [%4];"
                 : "=r"(r[0]), "=r"(r[1]), "=r"(r[2]), "=r"(r[3]) : "r"(addr));
}
static __device__ __forceinline__ void mma_bf16(float* d, const uint32_t* a,
                                                uint32_t b0, uint32_t b1) {
    asm volatile("mma.sync.aligned.m16n8k16.row.col.f32.bf16.bf16.f32 "
                 "{%0,%1,%2,%3}, {%4,%5,%6,%7}, {%8,%9}, {%0,%1,%2,%3};"
                 : "+f"(d[0]), "+f"(d[1]), "+f"(d[2]), "+f"(d[3])
                 : "r"(a[0]), "r"(a[1]), "r"(a[2]), "r"(a[3]), "r"(b0), "r"(b1));
}
static __device__ __forceinline__ float gate_of(int i) {
    float s = 0.f;
#pragma unroll
    for (int sl = 0; sl < 16; sl++) s += g_gatepart[sl][i];
    return (s * (1.0f / 131072.0f) > THRESH) ? 1.f : 0.f;
}

static __device__ __forceinline__ void split2(float a, float b, uint32_t& hp, uint32_t& lp) {
    asm("cvt.rn.bf16x2.f32 %0, %1, %2;" : "=r"(hp) : "f"(b), "f"(a));
    float ha = __uint_as_float(hp << 16);
    float hb = __uint_as_float(hp & 0xffff0000u);
    float la = a - ha;
    float lb = b - hb;
    asm("cvt.rn.bf16x2.f32 %0, %1, %2;" : "=r"(lp) : "f"(lb), "f"(la));
}
static __device__ __forceinline__ void split4(float4 f, uint2& h, uint2& l) {
    split2(f.x, f.y, h.x, l.x);
    split2(f.z, f.w, h.y, l.y);
}

// ---------------- init: zero accum + gate partials ----------------
__global__ void init_kernel(const float* __restrict__ Z) {
    int blk = blockIdx.x, t = threadIdx.x;
    int idx = blk * 256 + t;
    float4* p = (float4*)g_accum;
#pragma unroll
    for (int j = 0; j < 4; j++) p[idx * 4 + j] = make_float4(0.f, 0.f, 0.f, 0.f);

    if (blk < 64) {
        int area = blk & 3, slice = blk >> 2;
        float s = 0.f;
#pragma unroll
        for (int it = 0; it < 8; it++) {
            int f = t + 256 * it;
            int b = slice * 4 + (f >> 9), a4 = f & 511;
            float4 v = *(const float4*)(Z + (size_t)b * NTOT + (size_t)area * 2048 + a4 * 4);
            s += fabsf(v.x) + fabsf(v.y) + fabsf(v.z) + fabsf(v.w);
        }
#pragma unroll
        for (int o = 16; o; o >>= 1) s += __shfl_xor_sync(0xffffffffu, s, o);
        __shared__ float ws[8];
        if ((t & 31) == 0) ws[t >> 5] = s;
        __syncthreads();
        if (t == 0) {
            float tot = 0.f;
            for (int w = 0; w < 8; w++) tot += ws[w];
            g_gatepart[slice][area] = tot;
        }
    }
}

// ---------------- main HMMA kernel (occupancy 2) ----------------
__global__ __launch_bounds__(256, 2)
void main_kernel(const float* __restrict__ x, const float* __restrict__ Z,
                 const float* __restrict__ rw, const float* __restrict__ W,
                 const float* __restrict__ Mk)
{
    extern __shared__ char smem[];
    const uint32_t sb = smem_u32(smem);
    const int t = threadIdx.x, wid = t >> 5, lid = t & 31;
    const int ct = blockIdx.x >> 1;         // M-tile 0..127 (64 cols each)
    const int ks = blockIdx.x & 1;          // k-slice
    const int n0 = ct * MTILE;
    const int o = ct >> 5;                  // output area
    const int u0 = (ct & 31) * MTILE;

    float gates[4];
#pragma unroll
    for (int i = 0; i < 4; i++) gates[i] = gate_of(i);

    // coalesced loader indices
    const int lr16 = t >> 4;                // 0..15
    const int lk = t & 15;                  // float4 slot within KT

    float4 wv[4], mv[4], zv[4];
    uint2 ah2[4], al2[4], zh2[4], zl2[4];

    auto ldg = [&](int c) {
        if (c < 64) {                        // einsum
            int k0 = ks * 4096 + c * KT;
            int i = k0 >> 11, kl = k0 & 2047;
            const size_t base = ((size_t)(o * 4 + i) * 2048 + u0) * 2048 + kl + lk * 4;
#pragma unroll
            for (int v = 0; v < 4; v++) {
                size_t off = base + (size_t)(v * 16 + lr16) * 2048;
                wv[v] = *(const float4*)(W + off);
                mv[v] = *(const float4*)(Mk + off);
            }
#pragma unroll
            for (int v = 0; v < 4; v++)
                zv[v] = *(const float4*)(Z + (size_t)(v * 16 + lr16) * NTOT + k0 + lk * 4);
        } else {                             // stim
            int k0 = ks * 1536 + (c - 64) * KT;
#pragma unroll
            for (int v = 0; v < 4; v++)
                wv[v] = *(const float4*)(rw + (size_t)(n0 + v * 16 + lr16) * 3072 + k0 + lk * 4);
#pragma unroll
            for (int v = 0; v < 4; v++)
                zv[v] = *(const float4*)(x + (size_t)(v * 16 + lr16) * 3072 + k0 + lk * 4);
        }
    };

    auto cvtA = [&](int v, bool einsum) {
        float4 f = wv[v];
        if (einsum) {
            float4 m = mv[v];
            f.x *= __saturatef(m.x); f.y *= __saturatef(m.y);
            f.z *= __saturatef(m.z); f.w *= __saturatef(m.w);
        }
        split4(f, ah2[v], al2[v]);
    };
    auto cvtZ = [&](int v, float zg) {
        float4 f = zv[v];
        f.x *= zg; f.y *= zg; f.z *= zg; f.w *= zg;
        split4(f, zh2[v], zl2[v]);
    };

    auto sts = [&](uint32_t buf) {
#pragma unroll
        for (int v = 0; v < 4; v++) {
            uint32_t sw = SWZ((uint32_t)((v * 16 + lr16) * 128 + lk * 8));
            asm volatile("st.shared.v2.b32 [%0], {%1,%2};" ::
                         "r"(buf + AHI_OFF + sw), "r"(ah2[v].x), "r"(ah2[v].y) : "memory");
            asm volatile("st.shared.v2.b32 [%0], {%1,%2};" ::
                         "r"(buf + ALO_OFF + sw), "r"(al2[v].x), "r"(al2[v].y) : "memory");
            asm volatile("st.shared.v2.b32 [%0], {%1,%2};" ::
                         "r"(buf + BHI_OFF + sw), "r"(zh2[v].x), "r"(zh2[v].y) : "memory");
            asm volatile("st.shared.v2.b32 [%0], {%1,%2};" ::
                         "r"(buf + BLO_OFF + sw), "r"(zl2[v].x), "r"(zl2[v].y) : "memory");
        }
    };

    // warp tile: mw in 0..1 (32 cols), nw in 0..3 (16 batches)
    const int mw = wid & 1, nw = wid >> 1;
    const int lr = lid & 15, lh = lid >> 4;
    const uint32_t a_row0 = (uint32_t)((mw * 32 + lr) * 128 + lh * 16);
    const uint32_t a_row1 = a_row0 + 16 * 128;
    const uint32_t b_row  = (uint32_t)((nw * 16 + lr) * 128 + lh * 16);

    float acc[4][4];
#pragma unroll
    for (int i = 0; i < 4; i++)
#pragma unroll
        for (int j = 0; j < 4; j++) acc[i][j] = 0.f;

    auto mma_kk = [&](uint32_t buf, int kk) {
        const uint32_t ko = (uint32_t)(kk * 32);
        uint32_t ah0[4], ah1[4], al0[4], al1[4], bh[4], bl[4];
        ldsm4(ah0, buf + AHI_OFF + SWZ(a_row0 + ko));
        ldsm4(ah1, buf + AHI_OFF + SWZ(a_row1 + ko));
        ldsm4(bh,  buf + BHI_OFF + SWZ(b_row + ko));
        ldsm4(al0, buf + ALO_OFF + SWZ(a_row0 + ko));
        ldsm4(al1, buf + ALO_OFF + SWZ(a_row1 + ko));
        ldsm4(bl,  buf + BLO_OFF + SWZ(b_row + ko));
        // term 1: Ah x Bh
        mma_bf16(acc[0], ah0, bh[0], bh[2]);
        mma_bf16(acc[1], ah0, bh[1], bh[3]);
        mma_bf16(acc[2], ah1, bh[0], bh[2]);
        mma_bf16(acc[3], ah1, bh[1], bh[3]);
        // term 2: Ah x Bl
        mma_bf16(acc[0], ah0, bl[0], bl[2]);
        mma_bf16(acc[1], ah0, bl[1], bl[3]);
        mma_bf16(acc[2], ah1, bl[0], bl[2]);
        mma_bf16(acc[3], ah1, bl[1], bl[3]);
        // term 3: Al x Bh
        mma_bf16(acc[0], al0, bh[0], bh[2]);
        mma_bf16(acc[1], al0, bh[1], bh[3]);
        mma_bf16(acc[2], al1, bh[0], bh[2]);
        mma_bf16(acc[3], al1, bh[1], bh[3]);
    };

    // prologue: stage chunk 0
    ldg(0);
    {
        float zg0 = gates[(ks * 4096) >> 11];
#pragma unroll
        for (int v = 0; v < 4; v++) { cvtA(v, true); cvtZ(v, zg0); }
        sts(sb);
    }
    __syncthreads();

    for (int c = 0; c < HALF; c++) {
        const int p = c & 1;
        const uint32_t buf = sb + (uint32_t)p * BUFB;
        const uint32_t nbuf = sb + (uint32_t)(p ^ 1) * BUFB;
        const bool have_next = (c + 1 < HALF);
        bool ne = false; float nzg = 1.f;
        if (have_next) {
            ldg(c + 1);
            ne = (c + 1 < 64);
            nzg = ne ? gates[(ks * 4096 + (c + 1) * KT) >> 11] : 1.f;
        }
        mma_kk(buf, 0);
        mma_kk(buf, 1);
        mma_kk(buf, 2);
        if (have_next) { cvtA(0, ne); cvtA(1, ne); cvtZ(0, nzg); cvtZ(1, nzg); }
        mma_kk(buf, 3);
        if (have_next) {
            cvtA(2, ne); cvtA(3, ne); cvtZ(2, nzg); cvtZ(3, nzg);
            sts(nbuf);
        }
        __syncthreads();
    }

    // epilogue: spread atomics into g_accum
    const int mbase = n0 + mw * 32;
    const int r = lid >> 2, cp = (lid & 3) * 2;
#pragma unroll
    for (int mt = 0; mt < 2; mt++) {
#pragma unroll
        for (int nt = 0; nt < 2; nt++) {
            const float* cc = acc[mt * 2 + nt];
            int m = mbase + mt * 16 + r;
            int nb = nw * 16 + nt * 8 + cp;
            atomicAdd(&g_accum[(size_t)nb * NTOT + m],           cc[0]);
            atomicAdd(&g_accum[(size_t)(nb + 1) * NTOT + m],     cc[1]);
            atomicAdd(&g_accum[(size_t)nb * NTOT + m + 8],       cc[2]);
            atomicAdd(&g_accum[(size_t)(nb + 1) * NTOT + m + 8], cc[3]);
        }
    }
}

// ---------------- combine: bias/decay/tanh ----------------
__global__ void combine_kernel(const float* __restrict__ Z, const float* __restrict__ F,
                               const float* __restrict__ rb, const float* __restrict__ bias)
{
    int idx = blockIdx.x * 256 + threadIdx.x;
    int rest = idx & 2047;
    int n4 = rest * 4;
    int o = n4 >> 11;
    float g = gate_of(o);
    float4 a  = ((const float4*)g_accum)[idx];
    float4 rv = *(const float4*)(rb + n4);
    float4 bv = *(const float4*)(bias + n4);
    float4 Fv = ((const float4*)F)[idx];
    float4 Zv = ((const float4*)Z)[idx];
    float4 outv;
    outv.x = tanhf(a.x + rv.x + bv.x * g - 0.8f * Fv.x - 0.4f * Zv.x);
    outv.y = tanhf(a.y + rv.y + bv.y * g - 0.8f * Fv.y - 0.4f * Zv.y);
    outv.z = tanhf(a.z + rv.z + bv.z * g - 0.8f * Fv.z - 0.4f * Zv.z);
    outv.w = tanhf(a.w + rv.w + bv.w * g - 0.8f * Fv.w - 0.4f * Zv.w);
    ((float4*)g_znew)[idx] = outv;
}

// ---------------- output projection ----------------
__global__ void out_kernel(const float* __restrict__ out_w, const float* __restrict__ out_b,
                           float* __restrict__ out)
{
    int b = blockIdx.x, t = threadIdx.x;
    float p[11];
#pragma unroll
    for (int j = 0; j < 11; j++) p[j] = 0.f;
    const float4* zr = (const float4*)(g_znew + (size_t)b * NTOT);
#pragma unroll
    for (int it = 0; it < 8; it++) {
        int f4 = t + 256 * it;
        float4 z = zr[f4];
#pragma unroll
        for (int j = 0; j < 11; j++) {
            float4 w = ((const float4*)(out_w + (size_t)j * NTOT))[f4];
            p[j] += z.x * w.x + z.y * w.y + z.z * w.z + z.w * w.w;
        }
    }
    __shared__ float red[11 * 64];
#pragma unroll
    for (int j = 0; j < 11; j++) {
        float v = p[j];
#pragma unroll
        for (int o = 16; o; o >>= 1) v += __shfl_xor_sync(0xffffffffu, v, o);
        if ((t & 31) == 0) red[j * 64 + (t >> 5)] = v;
    }
    __syncthreads();
    if (t < 11) {
        float r = out_b[t];
        for (int w = 0; w < 8; w++) r += red[t * 64 + w];
        out[(size_t)b * 11 + t] = (t < 10) ? r : 1.0f / (1.0f + expf(-r));
    }
}

// ---------------- launch ----------------
extern "C" void kernel_launch(void* const* d_in, const int* in_sizes, int n_in,
                              void* d_out, int out_size) {
    const float* x      = (const float*)d_in[0];
    const float* Z      = (const float*)d_in[1];
    const float* Fstate = (const float*)d_in[2];
    const float* rw     = (const float*)d_in[3];
    const float* rb     = (const float*)d_in[4];
    const float* W      = (const float*)d_in[5];
    const float* Mk     = (const float*)d_in[6];
    const float* bias_d = (const float*)d_in[7];
    const float* out_w  = (const float*)d_in[8];
    const float* out_b  = (const float*)d_in[9];
    float* out = (float*)d_out;

    cudaFuncSetAttribute(main_kernel, cudaFuncAttributeMaxDynamicSharedMemorySize, SMEM_TOTAL);

    init_kernel<<<128, 256>>>(Z);
    main_kernel<<<256, 256, SMEM_TOTAL>>>(x, Z, rw, W, Mk);
    combine_kernel<<<512, 256>>>(Z, Fstate, rb, bias_d);
    out_kernel<<<NBATCH, 256>>>(out_w, out_b, out);
}

// round 11
// speedup vs baseline: 1.1305x; 1.0763x over previous
#include <cuda_runtime.h>
#include <cuda_bf16.h>
#include <cstdint>
#include <cstddef>

#define NBATCH 64
#define NTOT   8192
#define THRESH 0.02f
#define KT     64
#define MTILE  64
#define CPT    176                 // chunks per tile: 128 einsum + 48 stim
#define NTILE  128
#define TOTALW (NTILE * CPT)       // 22528 flat chunk-works
#define NCTA   296                 // 148 SMs x occ 2, single wave

// smem per buffer: Ahi 8K | Alo 8K | Bhi 8K | Blo 8K  (128B rows, SW128)
#define AHI_OFF 0
#define ALO_OFF 8192
#define BHI_OFF 16384
#define BLO_OFF 24576
#define BUFB    32768
#define SMEM_TOTAL (2 * BUFB)      // 65536 -> 2 CTAs/SM

__device__ float g_gatepart[16][4];
__device__ float g_accum[NBATCH * NTOT];
__device__ float g_znew[NBATCH * NTOT];
__device__ float g_outraw[NBATCH * 11];

// ---------------- helpers ----------------
static __device__ __forceinline__ uint32_t smem_u32(const void* p) {
    uint32_t a;
    asm("{ .reg .u64 t; cvta.to.shared.u64 t, %1; cvt.u32.u64 %0, t; }" : "=r"(a) : "l"(p));
    return a;
}
#define SWZ(o) ((o) ^ (((o) >> 3) & 0x70))

static __device__ __forceinline__ void ldsm4(uint32_t* r, uint32_t addr) {
    asm volatile("ldmatrix.sync.aligned.m8n8.x4.shared.b16 {%0,%1,%2,%3}, [%4];"
                 : "=r"(r[0]), "=r"(r[1]), "=r"(r[2]), "=r"(r[3]) : "r"(addr));
}
static __device__ __forceinline__ void mma_bf16(float* d, const uint32_t* a,
                                                uint32_t b0, uint32_t b1) {
    asm volatile("mma.sync.aligned.m16n8k16.row.col.f32.bf16.bf16.f32 "
                 "{%0,%1,%2,%3}, {%4,%5,%6,%7}, {%8,%9}, {%0,%1,%2,%3};"
                 : "+f"(d[0]), "+f"(d[1]), "+f"(d[2]), "+f"(d[3])
                 : "r"(a[0]), "r"(a[1]), "r"(a[2]), "r"(a[3]), "r"(b0), "r"(b1));
}
static __device__ __forceinline__ float gate_of(int i) {
    float s = 0.f;
#pragma unroll
    for (int sl = 0; sl < 16; sl++) s += g_gatepart[sl][i];
    return (s * (1.0f / 131072.0f) > THRESH) ? 1.f : 0.f;
}

static __device__ __forceinline__ void split2(float a, float b, uint32_t& hp, uint32_t& lp) {
    asm("cvt.rn.bf16x2.f32 %0, %1, %2;" : "=r"(hp) : "f"(b), "f"(a));
    float ha = __uint_as_float(hp << 16);
    float hb = __uint_as_float(hp & 0xffff0000u);
    float la = a - ha;
    float lb = b - hb;
    asm("cvt.rn.bf16x2.f32 %0, %1, %2;" : "=r"(lp) : "f"(lb), "f"(la));
}
static __device__ __forceinline__ void split4(float4 f, uint2& h, uint2& l) {
    split2(f.x, f.y, h.x, l.x);
    split2(f.z, f.w, h.y, l.y);
}

// ---------------- init: zero accum + outraw + gate partials ----------------
__global__ void init_kernel(const float* __restrict__ Z) {
    int blk = blockIdx.x, t = threadIdx.x;
    int idx = blk * 256 + t;
    float4* p = (float4*)g_accum;
#pragma unroll
    for (int j = 0; j < 4; j++) p[idx * 4 + j] = make_float4(0.f, 0.f, 0.f, 0.f);

    if (blk == 64) {
#pragma unroll
        for (int j = t; j < NBATCH * 11; j += 256) g_outraw[j] = 0.f;
    }
    if (blk < 64) {
        int area = blk & 3, slice = blk >> 2;
        float s = 0.f;
#pragma unroll
        for (int it = 0; it < 8; it++) {
            int f = t + 256 * it;
            int b = slice * 4 + (f >> 9), a4 = f & 511;
            float4 v = *(const float4*)(Z + (size_t)b * NTOT + (size_t)area * 2048 + a4 * 4);
            s += fabsf(v.x) + fabsf(v.y) + fabsf(v.z) + fabsf(v.w);
        }
#pragma unroll
        for (int o = 16; o; o >>= 1) s += __shfl_xor_sync(0xffffffffu, s, o);
        __shared__ float ws[8];
        if ((t & 31) == 0) ws[t >> 5] = s;
        __syncthreads();
        if (t == 0) {
            float tot = 0.f;
            for (int w = 0; w < 8; w++) tot += ws[w];
            g_gatepart[slice][area] = tot;
        }
    }
}

// ---------------- main HMMA kernel: flat balanced distribution ----------------
__global__ __launch_bounds__(256, 2)
void main_kernel(const float* __restrict__ x, const float* __restrict__ Z,
                 const float* __restrict__ rw, const float* __restrict__ W,
                 const float* __restrict__ Mk)
{
    extern __shared__ char smem[];
    const uint32_t sb = smem_u32(smem);
    const int t = threadIdx.x, wid = t >> 5, lid = t & 31;

    // flat work range for this CTA
    const int f0 = (int)((long long)blockIdx.x * TOTALW / NCTA);
    const int f1 = (int)((long long)(blockIdx.x + 1) * TOTALW / NCTA);

    float gates[4];
#pragma unroll
    for (int i = 0; i < 4; i++) gates[i] = gate_of(i);

    // coalesced loader indices
    const int lr16 = t >> 4;                // 0..15
    const int lk = t & 15;                  // float4 slot within KT

    float4 wv[4], mv[4], zv[4];
    uint2 ah2[4], al2[4], zh2[4], zl2[4];

    auto ldg = [&](int f) {
        int tile = f / CPT;
        int c = f - tile * CPT;
        int o = tile >> 5;
        int u0 = (tile & 31) * MTILE;
        if (c < 128) {                       // einsum chunk
            int k0 = c * KT;
            int i = k0 >> 11, kl = k0 & 2047;
            const size_t base = ((size_t)(o * 4 + i) * 2048 + u0) * 2048 + kl + lk * 4;
#pragma unroll
            for (int v = 0; v < 4; v++) {
                size_t off = base + (size_t)(v * 16 + lr16) * 2048;
                wv[v] = *(const float4*)(W + off);
                mv[v] = *(const float4*)(Mk + off);
            }
#pragma unroll
            for (int v = 0; v < 4; v++)
                zv[v] = *(const float4*)(Z + (size_t)(v * 16 + lr16) * NTOT + k0 + lk * 4);
        } else {                             // stim chunk
            int k0 = (c - 128) * KT;
            int n0 = tile * MTILE;
#pragma unroll
            for (int v = 0; v < 4; v++)
                wv[v] = *(const float4*)(rw + (size_t)(n0 + v * 16 + lr16) * 3072 + k0 + lk * 4);
#pragma unroll
            for (int v = 0; v < 4; v++)
                zv[v] = *(const float4*)(x + (size_t)(v * 16 + lr16) * 3072 + k0 + lk * 4);
        }
    };

    auto chunk_is_einsum = [&](int f) { return (f % CPT) < 128; };
    auto chunk_gate = [&](int f) {
        int c = f % CPT;
        return (c < 128) ? gates[c >> 5] : 1.f;
    };

    auto cvtA = [&](int v, bool einsum) {
        float4 f = wv[v];
        if (einsum) {
            float4 m = mv[v];
            f.x *= __saturatef(m.x); f.y *= __saturatef(m.y);
            f.z *= __saturatef(m.z); f.w *= __saturatef(m.w);
        }
        split4(f, ah2[v], al2[v]);
    };
    auto cvtZ = [&](int v, float zg) {
        float4 f = zv[v];
        f.x *= zg; f.y *= zg; f.z *= zg; f.w *= zg;
        split4(f, zh2[v], zl2[v]);
    };

    auto sts = [&](uint32_t buf) {
#pragma unroll
        for (int v = 0; v < 4; v++) {
            uint32_t sw = SWZ((uint32_t)((v * 16 + lr16) * 128 + lk * 8));
            asm volatile("st.shared.v2.b32 [%0], {%1,%2};" ::
                         "r"(buf + AHI_OFF + sw), "r"(ah2[v].x), "r"(ah2[v].y) : "memory");
            asm volatile("st.shared.v2.b32 [%0], {%1,%2};" ::
                         "r"(buf + ALO_OFF + sw), "r"(al2[v].x), "r"(al2[v].y) : "memory");
            asm volatile("st.shared.v2.b32 [%0], {%1,%2};" ::
                         "r"(buf + BHI_OFF + sw), "r"(zh2[v].x), "r"(zh2[v].y) : "memory");
            asm volatile("st.shared.v2.b32 [%0], {%1,%2};" ::
                         "r"(buf + BLO_OFF + sw), "r"(zl2[v].x), "r"(zl2[v].y) : "memory");
        }
    };

    // warp tile: mw in 0..1 (32 cols), nw in 0..3 (16 batches)
    const int mw = wid & 1, nw = wid >> 1;
    const int lr = lid & 15, lh = lid >> 4;
    const uint32_t a_row0 = (uint32_t)((mw * 32 + lr) * 128 + lh * 16);
    const uint32_t a_row1 = a_row0 + 16 * 128;
    const uint32_t b_row  = (uint32_t)((nw * 16 + lr) * 128 + lh * 16);

    float acc[4][4];
#pragma unroll
    for (int i = 0; i < 4; i++)
#pragma unroll
        for (int j = 0; j < 4; j++) acc[i][j] = 0.f;

    auto mma_kk = [&](uint32_t buf, int kk) {
        const uint32_t ko = (uint32_t)(kk * 32);
        uint32_t ah0[4], ah1[4], al0[4], al1[4], bh[4], bl[4];
        ldsm4(ah0, buf + AHI_OFF + SWZ(a_row0 + ko));
        ldsm4(ah1, buf + AHI_OFF + SWZ(a_row1 + ko));
        ldsm4(bh,  buf + BHI_OFF + SWZ(b_row + ko));
        ldsm4(al0, buf + ALO_OFF + SWZ(a_row0 + ko));
        ldsm4(al1, buf + ALO_OFF + SWZ(a_row1 + ko));
        ldsm4(bl,  buf + BLO_OFF + SWZ(b_row + ko));
        mma_bf16(acc[0], ah0, bh[0], bh[2]);
        mma_bf16(acc[1], ah0, bh[1], bh[3]);
        mma_bf16(acc[2], ah1, bh[0], bh[2]);
        mma_bf16(acc[3], ah1, bh[1], bh[3]);
        mma_bf16(acc[0], ah0, bl[0], bl[2]);
        mma_bf16(acc[1], ah0, bl[1], bl[3]);
        mma_bf16(acc[2], ah1, bl[0], bl[2]);
        mma_bf16(acc[3], ah1, bl[1], bl[3]);
        mma_bf16(acc[0], al0, bh[0], bh[2]);
        mma_bf16(acc[1], al0, bh[1], bh[3]);
        mma_bf16(acc[2], al1, bh[0], bh[2]);
        mma_bf16(acc[3], al1, bh[1], bh[3]);
    };

    // flush accumulator for a finished tile into g_accum
    const int r = lid >> 2, cp = (lid & 3) * 2;
    auto flush = [&](int tile) {
        int mbase = tile * MTILE + mw * 32;
#pragma unroll
        for (int mt = 0; mt < 2; mt++) {
#pragma unroll
            for (int nt = 0; nt < 2; nt++) {
                float* cc = acc[mt * 2 + nt];
                int m = mbase + mt * 16 + r;
                int nb = nw * 16 + nt * 8 + cp;
                atomicAdd(&g_accum[(size_t)nb * NTOT + m],           cc[0]);
                atomicAdd(&g_accum[(size_t)(nb + 1) * NTOT + m],     cc[1]);
                atomicAdd(&g_accum[(size_t)nb * NTOT + m + 8],       cc[2]);
                atomicAdd(&g_accum[(size_t)(nb + 1) * NTOT + m + 8], cc[3]);
                cc[0] = cc[1] = cc[2] = cc[3] = 0.f;
            }
        }
    };

    // prologue: stage chunk f0
    ldg(f0);
    {
        bool e0 = chunk_is_einsum(f0);
        float zg0 = chunk_gate(f0);
#pragma unroll
        for (int v = 0; v < 4; v++) { cvtA(v, e0); cvtZ(v, zg0); }
        sts(sb);
    }
    __syncthreads();

    for (int f = f0; f < f1; f++) {
        const int p = (f - f0) & 1;
        const uint32_t buf = sb + (uint32_t)p * BUFB;
        const uint32_t nbuf = sb + (uint32_t)(p ^ 1) * BUFB;
        const bool have_next = (f + 1 < f1);
        bool ne = false; float nzg = 1.f;
        if (have_next) {
            ldg(f + 1);
            ne = chunk_is_einsum(f + 1);
            nzg = chunk_gate(f + 1);
        }
        mma_kk(buf, 0);
        mma_kk(buf, 1);
        mma_kk(buf, 2);
        if (have_next) { cvtA(0, ne); cvtA(1, ne); cvtZ(0, nzg); cvtZ(1, nzg); }
        mma_kk(buf, 3);
        if (have_next) {
            cvtA(2, ne); cvtA(3, ne); cvtZ(2, nzg); cvtZ(3, nzg);
            sts(nbuf);
        }
        __syncthreads();

        // flush at tile boundary or end of range
        int tile = f / CPT;
        if (!have_next || ((f + 1) / CPT != tile)) flush(tile);
    }
}

// ---------------- combine: bias/decay/tanh ----------------
__global__ void combine_kernel(const float* __restrict__ Z, const float* __restrict__ F,
                               const float* __restrict__ rb, const float* __restrict__ bias)
{
    int idx = blockIdx.x * 256 + threadIdx.x;
    int rest = idx & 2047;
    int n4 = rest * 4;
    int o = n4 >> 11;
    float g = gate_of(o);
    float4 a  = ((const float4*)g_accum)[idx];
    float4 rv = *(const float4*)(rb + n4);
    float4 bv = *(const float4*)(bias + n4);
    float4 Fv = ((const float4*)F)[idx];
    float4 Zv = ((const float4*)Z)[idx];
    float4 outv;
    outv.x = tanhf(a.x + rv.x + bv.x * g - 0.8f * Fv.x - 0.4f * Zv.x);
    outv.y = tanhf(a.y + rv.y + bv.y * g - 0.8f * Fv.y - 0.4f * Zv.y);
    outv.z = tanhf(a.z + rv.z + bv.z * g - 0.8f * Fv.z - 0.4f * Zv.z);
    outv.w = tanhf(a.w + rv.w + bv.w * g - 0.8f * Fv.w - 0.4f * Zv.w);
    ((float4*)g_znew)[idx] = outv;
}

// ---------------- output projection: partials (256 blocks) + finalize ----------------
__global__ void out_part_kernel(const float* __restrict__ out_w)
{
    int b = blockIdx.x >> 2, sl = blockIdx.x & 3, t = threadIdx.x;
    float p[11];
#pragma unroll
    for (int j = 0; j < 11; j++) p[j] = 0.f;
    const float4* zr = (const float4*)(g_znew + (size_t)b * NTOT + sl * 2048);
#pragma unroll
    for (int it = 0; it < 2; it++) {
        int f4 = t + 256 * it;
        float4 z = zr[f4];
#pragma unroll
        for (int j = 0; j < 11; j++) {
            float4 w = ((const float4*)(out_w + (size_t)j * NTOT + sl * 2048))[f4];
            p[j] += z.x * w.x + z.y * w.y + z.z * w.z + z.w * w.w;
        }
    }
    __shared__ float red[11 * 8];
#pragma unroll
    for (int j = 0; j < 11; j++) {
        float v = p[j];
#pragma unroll
        for (int o = 16; o; o >>= 1) v += __shfl_xor_sync(0xffffffffu, v, o);
        if ((t & 31) == 0) red[j * 8 + (t >> 5)] = v;
    }
    __syncthreads();
    if (t < 11) {
        float s = 0.f;
#pragma unroll
        for (int w = 0; w < 8; w++) s += red[t * 8 + w];
        atomicAdd(&g_outraw[b * 11 + t], s);
    }
}

__global__ void out_fin_kernel(const float* __restrict__ out_b, float* __restrict__ out)
{
    int t = threadIdx.x;
    if (t < NBATCH * 11) {
        int j = t % 11;
        float r = g_outraw[t] + out_b[j];
        out[t] = (j < 10) ? r : 1.0f / (1.0f + expf(-r));
    }
}

// ---------------- launch ----------------
extern "C" void kernel_launch(void* const* d_in, const int* in_sizes, int n_in,
                              void* d_out, int out_size) {
    const float* x      = (const float*)d_in[0];
    const float* Z      = (const float*)d_in[1];
    const float* Fstate = (const float*)d_in[2];
    const float* rw     = (const float*)d_in[3];
    const float* rb     = (const float*)d_in[4];
    const float* W      = (const float*)d_in[5];
    const float* Mk     = (const float*)d_in[6];
    const float* bias_d = (const float*)d_in[7];
    const float* out_w  = (const float*)d_in[8];
    const float* out_b  = (const float*)d_in[9];
    float* out = (float*)d_out;

    cudaFuncSetAttribute(main_kernel, cudaFuncAttributeMaxDynamicSharedMemorySize, SMEM_TOTAL);

    init_kernel<<<128, 256>>>(Z);
    main_kernel<<<NCTA, 256, SMEM_TOTAL>>>(x, Z, rw, W, Mk);
    combine_kernel<<<512, 256>>>(Z, Fstate, rb, bias_d);
    out_part_kernel<<<256, 256>>>(out_w);
    out_fin_kernel<<<1, 704>>>(out_b, out);
}

// round 12
// speedup vs baseline: 1.3241x; 1.1713x over previous
#include <cuda_runtime.h>
#include <cuda_fp16.h>
#include <cstdint>
#include <cstddef>

#define NBATCH 64
#define NTOT   8192
#define THRESH 0.02f
#define KT     64
#define MTILE  64
#define CPT    176                 // chunks per tile: 128 einsum + 48 stim
#define NTILE  128
#define TOTALW (NTILE * CPT)       // 22528 flat chunk-works
#define NCTA   296                 // 148 SMs x occ 2, single wave

// smem per buffer: Ahi 8K | Alo 8K | Bh 8K  (128B rows, SW128)
#define AHI_OFF 0
#define ALO_OFF 8192
#define BH_OFF  16384
#define BUFB    24576
#define SMEM_TOTAL (2 * BUFB)      // 49152 -> 2 CTAs/SM

__device__ float g_gatepart[16][4];
__device__ float g_accum[NBATCH * NTOT];
__device__ float g_outraw[NBATCH * 11];

// ---------------- helpers ----------------
static __device__ __forceinline__ uint32_t smem_u32(const void* p) {
    uint32_t a;
    asm("{ .reg .u64 t; cvta.to.shared.u64 t, %1; cvt.u32.u64 %0, t; }" : "=r"(a) : "l"(p));
    return a;
}
#define SWZ(o) ((o) ^ (((o) >> 3) & 0x70))

static __device__ __forceinline__ void ldsm4(uint32_t* r, uint32_t addr) {
    asm volatile("ldmatrix.sync.aligned.m8n8.x4.shared.b16 {%0,%1,%2,%3}, [%4];"
                 : "=r"(r[0]), "=r"(r[1]), "=r"(r[2]), "=r"(r[3]) : "r"(addr));
}
static __device__ __forceinline__ void mma_f16(float* d, const uint32_t* a,
                                               uint32_t b0, uint32_t b1) {
    asm volatile("mma.sync.aligned.m16n8k16.row.col.f32.f16.f16.f32 "
                 "{%0,%1,%2,%3}, {%4,%5,%6,%7}, {%8,%9}, {%0,%1,%2,%3};"
                 : "+f"(d[0]), "+f"(d[1]), "+f"(d[2]), "+f"(d[3])
                 : "r"(a[0]), "r"(a[1]), "r"(a[2]), "r"(a[3]), "r"(b0), "r"(b1));
}
static __device__ __forceinline__ float gate_of(int i) {
    float s = 0.f;
#pragma unroll
    for (int sl = 0; sl < 16; sl++) s += g_gatepart[sl][i];
    return (s * (1.0f / 131072.0f) > THRESH) ? 1.f : 0.f;
}

// fp16 one-sided split: (a,b) -> hi pair + residual pair (lo half of reg = a)
static __device__ __forceinline__ void split2h(float a, float b, uint32_t& hp, uint32_t& lp) {
    asm("cvt.rn.f16x2.f32 %0, %1, %2;" : "=r"(hp) : "f"(b), "f"(a));
    __half2 h2 = *reinterpret_cast<__half2*>(&hp);
    float la = a - __low2float(h2);
    float lb = b - __high2float(h2);
    asm("cvt.rn.f16x2.f32 %0, %1, %2;" : "=r"(lp) : "f"(lb), "f"(la));
}
static __device__ __forceinline__ uint32_t pack2h(float a, float b) {
    uint32_t r;
    asm("cvt.rn.f16x2.f32 %0, %1, %2;" : "=r"(r) : "f"(b), "f"(a));
    return r;
}

// ---------------- init: zero accum + outraw + gate partials ----------------
__global__ void init_kernel(const float* __restrict__ Z) {
    int blk = blockIdx.x, t = threadIdx.x;
    int idx = blk * 256 + t;
    float4* p = (float4*)g_accum;
#pragma unroll
    for (int j = 0; j < 4; j++) p[idx * 4 + j] = make_float4(0.f, 0.f, 0.f, 0.f);

    if (blk == 64) {
        for (int j = t; j < NBATCH * 11; j += 256) g_outraw[j] = 0.f;
    }
    if (blk < 64) {
        int area = blk & 3, slice = blk >> 2;
        float s = 0.f;
#pragma unroll
        for (int it = 0; it < 8; it++) {
            int f = t + 256 * it;
            int b = slice * 4 + (f >> 9), a4 = f & 511;
            float4 v = *(const float4*)(Z + (size_t)b * NTOT + (size_t)area * 2048 + a4 * 4);
            s += fabsf(v.x) + fabsf(v.y) + fabsf(v.z) + fabsf(v.w);
        }
#pragma unroll
        for (int o = 16; o; o >>= 1) s += __shfl_xor_sync(0xffffffffu, s, o);
        __shared__ float ws[8];
        if ((t & 31) == 0) ws[t >> 5] = s;
        __syncthreads();
        if (t == 0) {
            float tot = 0.f;
            for (int w = 0; w < 8; w++) tot += ws[w];
            g_gatepart[slice][area] = tot;
        }
    }
}

// ---------------- main HMMA kernel: flat balanced distribution ----------------
__global__ __launch_bounds__(256, 2)
void main_kernel(const float* __restrict__ x, const float* __restrict__ Z,
                 const float* __restrict__ rw, const float* __restrict__ W,
                 const float* __restrict__ Mk)
{
    extern __shared__ char smem[];
    const uint32_t sb = smem_u32(smem);
    const int t = threadIdx.x, wid = t >> 5, lid = t & 31;

    const int f0 = (int)((long long)blockIdx.x * TOTALW / NCTA);
    const int f1 = (int)((long long)(blockIdx.x + 1) * TOTALW / NCTA);

    float gates[4];
#pragma unroll
    for (int i = 0; i < 4; i++) gates[i] = gate_of(i);

    const int lr16 = t >> 4;                // 0..15
    const int lk = t & 15;                  // float4 slot within KT

    float4 wv[4], mv[4], zv[4];
    uint2 ah2[4], al2[4], zh2[4];

    auto ldg = [&](int f) {
        int tile = f / CPT;
        int c = f - tile * CPT;
        int o = tile >> 5;
        int u0 = (tile & 31) * MTILE;
        if (c < 128) {                       // einsum chunk
            int k0 = c * KT;
            int i = k0 >> 11, kl = k0 & 2047;
            const size_t base = ((size_t)(o * 4 + i) * 2048 + u0) * 2048 + kl + lk * 4;
#pragma unroll
            for (int v = 0; v < 4; v++) {
                size_t off = base + (size_t)(v * 16 + lr16) * 2048;
                wv[v] = *(const float4*)(W + off);
                mv[v] = *(const float4*)(Mk + off);
            }
#pragma unroll
            for (int v = 0; v < 4; v++)
                zv[v] = *(const float4*)(Z + (size_t)(v * 16 + lr16) * NTOT + k0 + lk * 4);
        } else {                             // stim chunk
            int k0 = (c - 128) * KT;
            int n0 = tile * MTILE;
#pragma unroll
            for (int v = 0; v < 4; v++)
                wv[v] = *(const float4*)(rw + (size_t)(n0 + v * 16 + lr16) * 3072 + k0 + lk * 4);
#pragma unroll
            for (int v = 0; v < 4; v++)
                zv[v] = *(const float4*)(x + (size_t)(v * 16 + lr16) * 3072 + k0 + lk * 4);
        }
    };

    auto chunk_is_einsum = [&](int f) { return (f % CPT) < 128; };
    auto chunk_gate = [&](int f) {
        int c = f % CPT;
        return (c < 128) ? gates[c >> 5] : 1.f;
    };

    auto cvtA = [&](int v, bool einsum) {
        float4 f = wv[v];
        if (einsum) {
            float4 m = mv[v];
            f.x *= __saturatef(m.x); f.y *= __saturatef(m.y);
            f.z *= __saturatef(m.z); f.w *= __saturatef(m.w);
        }
        split2h(f.x, f.y, ah2[v].x, al2[v].x);
        split2h(f.z, f.w, ah2[v].y, al2[v].y);
    };
    auto cvtZ = [&](int v, float zg) {
        float4 f = zv[v];
        zh2[v].x = pack2h(f.x * zg, f.y * zg);
        zh2[v].y = pack2h(f.z * zg, f.w * zg);
    };

    auto sts = [&](uint32_t buf) {
#pragma unroll
        for (int v = 0; v < 4; v++) {
            uint32_t sw = SWZ((uint32_t)((v * 16 + lr16) * 128 + lk * 8));
            asm volatile("st.shared.v2.b32 [%0], {%1,%2};" ::
                         "r"(buf + AHI_OFF + sw), "r"(ah2[v].x), "r"(ah2[v].y) : "memory");
            asm volatile("st.shared.v2.b32 [%0], {%1,%2};" ::
                         "r"(buf + ALO_OFF + sw), "r"(al2[v].x), "r"(al2[v].y) : "memory");
            asm volatile("st.shared.v2.b32 [%0], {%1,%2};" ::
                         "r"(buf + BH_OFF + sw), "r"(zh2[v].x), "r"(zh2[v].y) : "memory");
        }
    };

    // warp tile: mw in 0..1 (32 cols), nw in 0..3 (16 batches)
    const int mw = wid & 1, nw = wid >> 1;
    const int lr = lid & 15, lh = lid >> 4;
    const uint32_t a_row0 = (uint32_t)((mw * 32 + lr) * 128 + lh * 16);
    const uint32_t a_row1 = a_row0 + 16 * 128;
    const uint32_t b_row  = (uint32_t)((nw * 16 + lr) * 128 + lh * 16);

    float acc[4][4];
#pragma unroll
    for (int i = 0; i < 4; i++)
#pragma unroll
        for (int j = 0; j < 4; j++) acc[i][j] = 0.f;

    auto mma_kk = [&](uint32_t buf, int kk) {
        const uint32_t ko = (uint32_t)(kk * 32);
        uint32_t ah0[4], ah1[4], al0[4], al1[4], bh[4];
        ldsm4(ah0, buf + AHI_OFF + SWZ(a_row0 + ko));
        ldsm4(ah1, buf + AHI_OFF + SWZ(a_row1 + ko));
        ldsm4(bh,  buf + BH_OFF  + SWZ(b_row + ko));
        ldsm4(al0, buf + ALO_OFF + SWZ(a_row0 + ko));
        ldsm4(al1, buf + ALO_OFF + SWZ(a_row1 + ko));
        // term 1: Ah x Bh
        mma_f16(acc[0], ah0, bh[0], bh[2]);
        mma_f16(acc[1], ah0, bh[1], bh[3]);
        mma_f16(acc[2], ah1, bh[0], bh[2]);
        mma_f16(acc[3], ah1, bh[1], bh[3]);
        // term 2: Al x Bh
        mma_f16(acc[0], al0, bh[0], bh[2]);
        mma_f16(acc[1], al0, bh[1], bh[3]);
        mma_f16(acc[2], al1, bh[0], bh[2]);
        mma_f16(acc[3], al1, bh[1], bh[3]);
    };

    const int r = lid >> 2, cp = (lid & 3) * 2;
    auto flush = [&](int tile) {
        int mbase = tile * MTILE + mw * 32;
#pragma unroll
        for (int mt = 0; mt < 2; mt++) {
#pragma unroll
            for (int nt = 0; nt < 2; nt++) {
                float* cc = acc[mt * 2 + nt];
                int m = mbase + mt * 16 + r;
                int nb = nw * 16 + nt * 8 + cp;
                atomicAdd(&g_accum[(size_t)nb * NTOT + m],           cc[0]);
                atomicAdd(&g_accum[(size_t)(nb + 1) * NTOT + m],     cc[1]);
                atomicAdd(&g_accum[(size_t)nb * NTOT + m + 8],       cc[2]);
                atomicAdd(&g_accum[(size_t)(nb + 1) * NTOT + m + 8], cc[3]);
                cc[0] = cc[1] = cc[2] = cc[3] = 0.f;
            }
        }
    };

    // prologue
    ldg(f0);
    {
        bool e0 = chunk_is_einsum(f0);
        float zg0 = chunk_gate(f0);
#pragma unroll
        for (int v = 0; v < 4; v++) { cvtA(v, e0); cvtZ(v, zg0); }
        sts(sb);
    }
    __syncthreads();

    for (int f = f0; f < f1; f++) {
        const int p = (f - f0) & 1;
        const uint32_t buf = sb + (uint32_t)p * BUFB;
        const uint32_t nbuf = sb + (uint32_t)(p ^ 1) * BUFB;
        const bool have_next = (f + 1 < f1);
        bool ne = false; float nzg = 1.f;
        if (have_next) {
            ldg(f + 1);
            ne = chunk_is_einsum(f + 1);
            nzg = chunk_gate(f + 1);
        }
        mma_kk(buf, 0);
        mma_kk(buf, 1);
        mma_kk(buf, 2);
        if (have_next) { cvtA(0, ne); cvtA(1, ne); cvtZ(0, nzg); cvtZ(1, nzg); }
        mma_kk(buf, 3);
        if (have_next) {
            cvtA(2, ne); cvtA(3, ne); cvtZ(2, nzg); cvtZ(3, nzg);
            sts(nbuf);
        }
        __syncthreads();

        int tile = f / CPT;
        if (!have_next || ((f + 1) / CPT != tile)) flush(tile);
    }
}

// ---------------- combine + output partials fused ----------------
__global__ void combine_out_kernel(const float* __restrict__ Z, const float* __restrict__ F,
                                   const float* __restrict__ rb, const float* __restrict__ bias,
                                   const float* __restrict__ out_w)
{
    int idx = blockIdx.x * 256 + threadIdx.x;   // float4 index over [64][8192]
    int b = blockIdx.x >> 3;                    // 8 blocks per batch row
    int rest = idx & 2047;
    int n4 = rest * 4;
    int o = n4 >> 11;
    float g = gate_of(o);
    float4 a  = ((const float4*)g_accum)[idx];
    float4 rv = *(const float4*)(rb + n4);
    float4 bv = *(const float4*)(bias + n4);
    float4 Fv = ((const float4*)F)[idx];
    float4 Zv = ((const float4*)Z)[idx];
    float4 zn;
    zn.x = tanhf(a.x + rv.x + bv.x * g - 0.8f * Fv.x - 0.4f * Zv.x);
    zn.y = tanhf(a.y + rv.y + bv.y * g - 0.8f * Fv.y - 0.4f * Zv.y);
    zn.z = tanhf(a.z + rv.z + bv.z * g - 0.8f * Fv.z - 0.4f * Zv.z);
    zn.w = tanhf(a.w + rv.w + bv.w * g - 0.8f * Fv.w - 0.4f * Zv.w);

    float p[11];
#pragma unroll
    for (int j = 0; j < 11; j++) {
        float4 w = *(const float4*)(out_w + (size_t)j * NTOT + n4);
        p[j] = zn.x * w.x + zn.y * w.y + zn.z * w.z + zn.w * w.w;
    }
    __shared__ float red[11 * 8];
    int t = threadIdx.x;
#pragma unroll
    for (int j = 0; j < 11; j++) {
        float v = p[j];
#pragma unroll
        for (int of = 16; of; of >>= 1) v += __shfl_xor_sync(0xffffffffu, v, of);
        if ((t & 31) == 0) red[j * 8 + (t >> 5)] = v;
    }
    __syncthreads();
    if (t < 11) {
        float s = 0.f;
#pragma unroll
        for (int w = 0; w < 8; w++) s += red[t * 8 + w];
        atomicAdd(&g_outraw[b * 11 + t], s);
    }
}

__global__ void out_fin_kernel(const float* __restrict__ out_b, float* __restrict__ out)
{
    int t = threadIdx.x;
    if (t < NBATCH * 11) {
        int j = t % 11;
        float r = g_outraw[t] + out_b[j];
        out[t] = (j < 10) ? r : 1.0f / (1.0f + expf(-r));
    }
}

// ---------------- launch ----------------
extern "C" void kernel_launch(void* const* d_in, const int* in_sizes, int n_in,
                              void* d_out, int out_size) {
    const float* x      = (const float*)d_in[0];
    const float* Z      = (const float*)d_in[1];
    const float* Fstate = (const float*)d_in[2];
    const float* rw     = (const float*)d_in[3];
    const float* rb     = (const float*)d_in[4];
    const float* W      = (const float*)d_in[5];
    const float* Mk     = (const float*)d_in[6];
    const float* bias_d = (const float*)d_in[7];
    const float* out_w  = (const float*)d_in[8];
    const float* out_b  = (const float*)d_in[9];
    float* out = (float*)d_out;

    cudaFuncSetAttribute(main_kernel, cudaFuncAttributeMaxDynamicSharedMemorySize, SMEM_TOTAL);

    init_kernel<<<128, 256>>>(Z);
    main_kernel<<<NCTA, 256, SMEM_TOTAL>>>(x, Z, rw, W, Mk);
    combine_out_kernel<<<512, 256>>>(Z, Fstate, rb, bias_d, out_w);
    out_fin_kernel<<<1, 704>>>(out_b, out);
}